// round 2
// baseline (speedup 1.0000x reference)
#include <cuda_runtime.h>
#include <math.h>

#define T 1024
#define HD 1024
#define FD 1024
#define NE 32
#define TOPK 4
#define NPAIR (T*TOPK)

#define BM 64
#define BK 32
#define BN 128
#define MT_MAX 96

// ---------------- scratch (device globals: allocation-free) ----------------
__device__ float g_t[T*HD];                 // rmsnormed tokens (4 MB)
__device__ float g_wt[NPAIR];               // routing weight per (token,slot)
__device__ int   g_eid[NPAIR];              // expert per (token,slot)
__device__ int   g_cnt[NE];
__device__ int   g_pos[NE];
__device__ int   g_off[NE+1];
__device__ int   g_perm[NPAIR];             // pair ids grouped by expert
__device__ int   g_tile_e[MT_MAX];
__device__ int   g_tile_row[MT_MAX];
__device__ int   g_tile_cnt[MT_MAX];
__device__ int   g_numtiles;
__device__ float g_act[(size_t)NPAIR*FD];   // weighted swiglu output (16 MB)

// ---------------- init: residual copy + zero counters ----------------
__global__ void init_kernel(const float* __restrict__ x, float* __restrict__ out){
    int i = blockIdx.x*blockDim.x + threadIdx.x;
    if (i < T*HD) out[i] = x[i];
    if (i < NE) { g_cnt[i] = 0; g_pos[i] = 0; }
}

// ---------------- rmsnorm + gate + top-4 + softmax ----------------
__global__ void route_kernel(const float* __restrict__ x,
                             const float* __restrict__ nscale,
                             const float* __restrict__ gw,
                             const float* __restrict__ gb){
    int t  = blockIdx.x;
    int tx = threadIdx.x;
    __shared__ float sT[HD];
    __shared__ float sred[256];
    __shared__ float slog[NE];
    const float* xr = x + (size_t)t*HD;

    float ss = 0.f;
    for (int i = tx; i < HD; i += 256){ float v = xr[i]; sT[i] = v; ss += v*v; }
    sred[tx] = ss; __syncthreads();
    for (int s = 128; s > 0; s >>= 1){ if (tx < s) sred[tx] += sred[tx+s]; __syncthreads(); }
    float r = rsqrtf(sred[0]/(float)HD + 1e-5f);
    __syncthreads();
    for (int i = tx; i < HD; i += 256){
        float v = sT[i]*r*nscale[i];
        sT[i] = v;
        g_t[(size_t)t*HD + i] = v;
    }
    __syncthreads();

    // 8 lanes per expert: warp w handles experts 4w..4w+3
    int e  = (tx>>5)*4 + ((tx&31)>>3);
    int li = tx & 7;
    const float* gwr = gw + (size_t)e*HD;
    float p = 0.f;
    for (int i = li; i < HD; i += 8) p += sT[i]*gwr[i];
    p += __shfl_down_sync(0xffffffffu, p, 4, 8);
    p += __shfl_down_sync(0xffffffffu, p, 2, 8);
    p += __shfl_down_sync(0xffffffffu, p, 1, 8);
    if (li == 0) slog[e] = p + gb[e];
    __syncthreads();

    if (tx == 0){
        float l[NE];
        #pragma unroll
        for (int i = 0; i < NE; i++) l[i] = slog[i];
        float v[TOPK]; int id[TOPK];
        #pragma unroll
        for (int k = 0; k < TOPK; k++){
            float best = -1e30f; int bi = 0;
            for (int i = 0; i < NE; i++) if (l[i] > best){ best = l[i]; bi = i; }
            v[k] = best; id[k] = bi; l[bi] = -1e30f;
        }
        float m = v[0], s = 0.f, w4[TOPK];
        #pragma unroll
        for (int k = 0; k < TOPK; k++){ w4[k] = expf(v[k]-m); s += w4[k]; }
        float inv = 1.f/s;
        #pragma unroll
        for (int k = 0; k < TOPK; k++){
            int pr = t*TOPK + k;
            g_wt[pr]  = w4[k]*inv;
            g_eid[pr] = id[k];
            atomicAdd(&g_cnt[id[k]], 1);
        }
    }
}

// ---------------- offsets + M-tile table (trivial serial) ----------------
__global__ void scan_kernel(){
    int off = 0, nt = 0;
    for (int e = 0; e < NE; e++){
        g_off[e] = off;
        int c = g_cnt[e];
        for (int r2 = 0; r2 < c; r2 += BM){
            g_tile_e[nt]   = e;
            g_tile_row[nt] = off + r2;
            g_tile_cnt[nt] = min(BM, c - r2);
            nt++;
        }
        off += c;
    }
    g_off[NE]  = off;
    g_numtiles = nt;
}

__global__ void scatter_kernel(){
    int p = blockIdx.x*blockDim.x + threadIdx.x;
    if (p < NPAIR){
        int e = g_eid[p];
        int pos = g_off[e] + atomicAdd(&g_pos[e], 1);
        g_perm[pos] = p;
    }
}

// ---------------- mlp1 + swiglu (grouped GEMM, weight folded) ----------------
__global__ __launch_bounds__(256) void mlp1_kernel(const float* __restrict__ w1,
                                                   const float* __restrict__ b1){
    int mt = blockIdx.x;
    if (mt >= g_numtiles) return;
    int e        = g_tile_e[mt];
    int rowstart = g_tile_row[mt];
    int rcnt     = g_tile_cnt[mt];
    int nb       = blockIdx.y;           // 16 tiles of 128 w1 rows

    __shared__ float smA[BK][BM+1];
    __shared__ float smW[BN][BK+1];
    __shared__ int   sPair[BM];
    __shared__ float sWgt[BM];

    int tx = threadIdx.x;
    if (tx < BM){
        int p = (tx < rcnt) ? g_perm[rowstart + tx] : -1;
        sPair[tx] = p;
        sWgt[tx]  = (p >= 0) ? g_wt[p] : 0.f;
    }
    __syncthreads();

    int tm = tx & 15, tn = tx >> 4;
    int m0 = tm*4,   n0 = tn*8;
    const float* W = w1 + (size_t)e*(2*FD)*HD + (size_t)(nb*BN)*HD;

    float acc[4][8];
    #pragma unroll
    for (int i = 0; i < 4; i++)
        #pragma unroll
        for (int j = 0; j < 8; j++) acc[i][j] = 0.f;

    for (int kk = 0; kk < HD; kk += BK){
        #pragma unroll
        for (int i = 0; i < 8; i++){
            int idx = tx + i*256, r2 = idx>>5, c = idx&31;
            int p = sPair[r2];
            smA[c][r2] = (p >= 0) ? g_t[(size_t)(p>>2)*HD + kk + c] : 0.f;
        }
        #pragma unroll
        for (int i = 0; i < 16; i++){
            int idx = tx + i*256, r2 = idx>>5, c = idx&31;
            smW[r2][c] = W[(size_t)r2*HD + kk + c];
        }
        __syncthreads();
        #pragma unroll 8
        for (int k = 0; k < BK; k++){
            float a0 = smA[k][m0+0], a1 = smA[k][m0+1];
            float a2 = smA[k][m0+2], a3 = smA[k][m0+3];
            #pragma unroll
            for (int j = 0; j < 8; j++){
                float w = smW[n0+j][k];
                acc[0][j] += a0*w; acc[1][j] += a1*w;
                acc[2][j] += a2*w; acc[3][j] += a3*w;
            }
        }
        __syncthreads();
    }

    int rowbase = nb*BN + n0;            // even; 8 rows = 4 glu/lin pairs
    const float* b1e = b1 + (size_t)e*(2*FD);
    #pragma unroll
    for (int m = 0; m < 4; m++){
        int r2 = m0 + m;
        int p = sPair[r2];
        if (p < 0) continue;
        float wg = sWgt[r2];
        float* dst = g_act + (size_t)p*FD + (rowbase>>1);
        #pragma unroll
        for (int j = 0; j < 4; j++){
            float glu = acc[m][2*j]   + b1e[rowbase + 2*j];
            float lin = acc[m][2*j+1] + b1e[rowbase + 2*j + 1];
            glu = fminf(glu, 7.0f);
            lin = fminf(fmaxf(lin, -7.0f), 7.0f);
            float sg = 1.f/(1.f + expf(-1.702f*glu));
            dst[j] = glu*sg*(lin + 1.f)*wg;
        }
    }
}

// ---------------- mlp2 + scatter-add into residual ----------------
__global__ __launch_bounds__(256) void mlp2_kernel(const float* __restrict__ w2,
                                                   const float* __restrict__ b2,
                                                   float* __restrict__ out){
    int mt = blockIdx.x;
    if (mt >= g_numtiles) return;
    int e        = g_tile_e[mt];
    int rowstart = g_tile_row[mt];
    int rcnt     = g_tile_cnt[mt];
    int nb       = blockIdx.y;           // 8 tiles of 128 H outputs

    __shared__ float smA[BK][BM+1];
    __shared__ float smW[BN][BK+1];
    __shared__ int   sPair[BM];
    __shared__ float sWgt[BM];

    int tx = threadIdx.x;
    if (tx < BM){
        int p = (tx < rcnt) ? g_perm[rowstart + tx] : -1;
        sPair[tx] = p;
        sWgt[tx]  = (p >= 0) ? g_wt[p] : 0.f;
    }
    __syncthreads();

    int tm = tx & 15, tn = tx >> 4;
    int m0 = tm*4,   n0 = tn*8;
    const float* W = w2 + (size_t)e*HD*FD + (size_t)(nb*BN)*FD;

    float acc[4][8];
    #pragma unroll
    for (int i = 0; i < 4; i++)
        #pragma unroll
        for (int j = 0; j < 8; j++) acc[i][j] = 0.f;

    for (int kk = 0; kk < FD; kk += BK){
        #pragma unroll
        for (int i = 0; i < 8; i++){
            int idx = tx + i*256, r2 = idx>>5, c = idx&31;
            int p = sPair[r2];
            smA[c][r2] = (p >= 0) ? g_act[(size_t)p*FD + kk + c] : 0.f;
        }
        #pragma unroll
        for (int i = 0; i < 16; i++){
            int idx = tx + i*256, r2 = idx>>5, c = idx&31;
            smW[r2][c] = W[(size_t)r2*FD + kk + c];
        }
        __syncthreads();
        #pragma unroll 8
        for (int k = 0; k < BK; k++){
            float a0 = smA[k][m0+0], a1 = smA[k][m0+1];
            float a2 = smA[k][m0+2], a3 = smA[k][m0+3];
            #pragma unroll
            for (int j = 0; j < 8; j++){
                float w = smW[n0+j][k];
                acc[0][j] += a0*w; acc[1][j] += a1*w;
                acc[2][j] += a2*w; acc[3][j] += a3*w;
            }
        }
        __syncthreads();
    }

    int hbase = nb*BN + n0;
    const float* b2e = b2 + (size_t)e*HD;
    #pragma unroll
    for (int m = 0; m < 4; m++){
        int r2 = m0 + m;
        int p = sPair[r2];
        if (p < 0) continue;
        int t = p >> 2;
        float wg = sWgt[r2];
        #pragma unroll
        for (int j = 0; j < 8; j++){
            int h = hbase + j;
            float val = acc[m][j] + wg*b2e[h];
            atomicAdd(&out[(size_t)t*HD + h], val);
        }
    }
}

// ---------------- launch ----------------
extern "C" void kernel_launch(void* const* d_in, const int* in_sizes, int n_in,
                              void* d_out, int out_size){
    const float* x      = (const float*)d_in[0];
    const float* nscale = (const float*)d_in[1];
    const float* gw     = (const float*)d_in[2];
    const float* gb     = (const float*)d_in[3];
    const float* w1     = (const float*)d_in[4];
    const float* b1     = (const float*)d_in[5];
    const float* w2     = (const float*)d_in[6];
    const float* b2     = (const float*)d_in[7];
    float* out = (float*)d_out;

    init_kernel   <<<(T*HD + 255)/256, 256>>>(x, out);
    route_kernel  <<<T, 256>>>(x, nscale, gw, gb);
    scan_kernel   <<<1, 1>>>();
    scatter_kernel<<<(NPAIR + 255)/256, 256>>>();
    mlp1_kernel   <<<dim3(MT_MAX, (2*FD)/BN), 256>>>(w1, b1);
    mlp2_kernel   <<<dim3(MT_MAX, HD/BN),     256>>>(w2, b2, out);
}

// round 3
// speedup vs baseline: 4.4091x; 4.4091x over previous
#include <cuda_runtime.h>
#include <math.h>

#define T 1024
#define HD 1024
#define FD 1024
#define NE 32
#define TOPK 4
#define NPAIR (T*TOPK)

#define BM 128
#define BN 128
#define BK 32
#define LDA 36              // padded row stride (floats), 16B-aligned, conflict-free
#define MT_MAX 64           // sum ceil(cnt_e/128) <= 32 + 32

// ---------------- scratch ----------------
__device__ float g_t[T*HD];
__device__ float g_wt[NPAIR];
__device__ int   g_eid[NPAIR];
__device__ int   g_cnt[NE];
__device__ int   g_pos[NE];
__device__ int   g_off[NE+1];
__device__ int   g_perm[NPAIR];
__device__ int   g_tile_e[MT_MAX];
__device__ int   g_tile_row[MT_MAX];
__device__ int   g_tile_cnt[MT_MAX];
__device__ int   g_numtiles;
__device__ float g_act[(size_t)NPAIR*FD];

// ---------------- helpers ----------------
__device__ __forceinline__ void cp_async16(unsigned saddr, const void* g, int sz){
    asm volatile("cp.async.cg.shared.global [%0], [%1], 16, %2;\n"
                 :: "r"(saddr), "l"(g), "r"(sz));
}
__device__ __forceinline__ void cp_commit(){ asm volatile("cp.async.commit_group;\n"); }
template<int N>
__device__ __forceinline__ void cp_wait(){ asm volatile("cp.async.wait_group %0;\n"::"n"(N)); }

__device__ __forceinline__ void mma8(float* d, const unsigned* a, const unsigned* b){
    asm volatile("mma.sync.aligned.m16n8k8.row.col.f32.tf32.tf32.f32 "
                 "{%0,%1,%2,%3},{%4,%5,%6,%7},{%8,%9},{%0,%1,%2,%3};\n"
                 : "+f"(d[0]), "+f"(d[1]), "+f"(d[2]), "+f"(d[3])
                 : "r"(a[0]), "r"(a[1]), "r"(a[2]), "r"(a[3]),
                   "r"(b[0]), "r"(b[1]));
}

// ---------------- init ----------------
__global__ void init_kernel(const float* __restrict__ x, float* __restrict__ out){
    int i = blockIdx.x*blockDim.x + threadIdx.x;
    if (i < T*HD) out[i] = x[i];
    if (i < NE) { g_cnt[i] = 0; g_pos[i] = 0; }
}

// ---------------- rmsnorm + gate + top-4 + softmax ----------------
__global__ void route_kernel(const float* __restrict__ x,
                             const float* __restrict__ nscale,
                             const float* __restrict__ gw,
                             const float* __restrict__ gb){
    int t  = blockIdx.x;
    int tx = threadIdx.x;
    __shared__ float sT[HD];
    __shared__ float sred[256];
    __shared__ float slog[NE];
    const float* xr = x + (size_t)t*HD;

    float ss = 0.f;
    for (int i = tx; i < HD; i += 256){ float v = xr[i]; sT[i] = v; ss += v*v; }
    sred[tx] = ss; __syncthreads();
    for (int s = 128; s > 0; s >>= 1){ if (tx < s) sred[tx] += sred[tx+s]; __syncthreads(); }
    float r = rsqrtf(sred[0]/(float)HD + 1e-5f);
    __syncthreads();
    for (int i = tx; i < HD; i += 256){
        float v = sT[i]*r*nscale[i];
        sT[i] = v;
        g_t[(size_t)t*HD + i] = v;
    }
    __syncthreads();

    int e  = (tx>>5)*4 + ((tx&31)>>3);
    int li = tx & 7;
    const float* gwr = gw + (size_t)e*HD;
    float p = 0.f;
    for (int i = li; i < HD; i += 8) p += sT[i]*gwr[i];
    p += __shfl_down_sync(0xffffffffu, p, 4, 8);
    p += __shfl_down_sync(0xffffffffu, p, 2, 8);
    p += __shfl_down_sync(0xffffffffu, p, 1, 8);
    if (li == 0) slog[e] = p + gb[e];
    __syncthreads();

    if (tx == 0){
        float l[NE];
        #pragma unroll
        for (int i = 0; i < NE; i++) l[i] = slog[i];
        float v[TOPK]; int id[TOPK];
        #pragma unroll
        for (int k = 0; k < TOPK; k++){
            float best = -1e30f; int bi = 0;
            for (int i = 0; i < NE; i++) if (l[i] > best){ best = l[i]; bi = i; }
            v[k] = best; id[k] = bi; l[bi] = -1e30f;
        }
        float m = v[0], s = 0.f, w4[TOPK];
        #pragma unroll
        for (int k = 0; k < TOPK; k++){ w4[k] = expf(v[k]-m); s += w4[k]; }
        float inv = 1.f/s;
        #pragma unroll
        for (int k = 0; k < TOPK; k++){
            int pr = t*TOPK + k;
            g_wt[pr]  = w4[k]*inv;
            g_eid[pr] = id[k];
            atomicAdd(&g_cnt[id[k]], 1);
        }
    }
}

// ---------------- offsets + tiles ----------------
__global__ void scan_kernel(){
    int off = 0, nt = 0;
    for (int e = 0; e < NE; e++){
        g_off[e] = off;
        int c = g_cnt[e];
        for (int r2 = 0; r2 < c; r2 += BM){
            g_tile_e[nt]   = e;
            g_tile_row[nt] = off + r2;
            g_tile_cnt[nt] = min(BM, c - r2);
            nt++;
        }
        off += c;
    }
    g_off[NE]  = off;
    g_numtiles = nt;
}

__global__ void scatter_kernel(){
    int p = blockIdx.x*blockDim.x + threadIdx.x;
    if (p < NPAIR){
        int e = g_eid[p];
        int pos = g_off[e] + atomicAdd(&g_pos[e], 1);
        g_perm[pos] = p;
    }
}

// ============ shared GEMM mainloop (tf32 mma, double-buffered cp.async) ============
// smem layout: sA[2][128][LDA], sB[2][128][LDA], sPair[128], sWgt[128]
#define STAGE_F (BM*LDA)

struct Frag { float acc[4][4][4]; };

__device__ __forceinline__ void gemm_mainloop(
    float* sA, float* sB, const int* sPair,
    const float* __restrict__ Asrc, int a_is_token,   // 1: row index = pair>>2 (g_t), 0: row = pair (g_act)
    const float* __restrict__ W,                      // weight block base, row-major [*,1024]
    Frag& fr, int tx)
{
    const int rowL = tx >> 3;          // 0..31 (advance by 32 per j)
    const int segL = tx & 7;
    const unsigned* sAu = (const unsigned*)sA;
    const unsigned* sBu = (const unsigned*)sB;

    unsigned sA_addr = (unsigned)__cvta_generic_to_shared(sA);
    unsigned sB_addr = (unsigned)__cvta_generic_to_shared(sB);

    int w  = tx >> 5, lane = tx & 31;
    int g  = lane >> 2, t4 = lane & 3;
    int wm = w & 1, wn = w >> 1;

    #pragma unroll
    for (int mt = 0; mt < 4; mt++)
        #pragma unroll
        for (int nt = 0; nt < 4; nt++)
            #pragma unroll
            for (int i = 0; i < 4; i++) fr.acc[mt][nt][i] = 0.f;

    // ---- prologue: stage 0 ----
    {
        #pragma unroll
        for (int j = 0; j < 4; j++){
            int row = rowL + 32*j;
            int p = sPair[row];
            int valid = (p >= 0);
            long arow = a_is_token ? (long)(p >> 2) : (long)p;
            const float* src = valid ? (Asrc + arow*1024 + segL*4) : Asrc;
            cp_async16(sA_addr + (row*LDA + segL*4)*4, src, valid ? 16 : 0);
        }
        #pragma unroll
        for (int j = 0; j < 4; j++){
            int row = rowL + 32*j;
            cp_async16(sB_addr + (row*LDA + segL*4)*4, W + (size_t)row*1024 + segL*4, 16);
        }
        cp_commit();
    }

    const int NIT = 1024/BK;
    for (int it = 0; it < NIT; it++){
        int buf = it & 1;
        if (it + 1 < NIT){
            int nb2 = (it+1) & 1;
            int kk  = (it+1)*BK;
            #pragma unroll
            for (int j = 0; j < 4; j++){
                int row = rowL + 32*j;
                int p = sPair[row];
                int valid = (p >= 0);
                long arow = a_is_token ? (long)(p >> 2) : (long)p;
                const float* src = valid ? (Asrc + arow*1024 + kk + segL*4) : Asrc;
                cp_async16(sA_addr + (nb2*STAGE_F + row*LDA + segL*4)*4, src, valid ? 16 : 0);
            }
            #pragma unroll
            for (int j = 0; j < 4; j++){
                int row = rowL + 32*j;
                cp_async16(sB_addr + (nb2*STAGE_F + row*LDA + segL*4)*4,
                           W + (size_t)row*1024 + kk + segL*4, 16);
            }
            cp_commit();
            cp_wait<1>();
        } else {
            cp_wait<0>();
        }
        __syncthreads();

        const unsigned* A0 = sAu + buf*STAGE_F;
        const unsigned* B0 = sBu + buf*STAGE_F;
        #pragma unroll
        for (int ks = 0; ks < 4; ks++){
            unsigned afr[4][4], bfr[4][2];
            #pragma unroll
            for (int mt = 0; mt < 4; mt++){
                int r0 = (wm*64 + mt*16 + g)*LDA + ks*8 + t4;
                afr[mt][0] = A0[r0];
                afr[mt][1] = A0[r0 + 8*LDA];
                afr[mt][2] = A0[r0 + 4];
                afr[mt][3] = A0[r0 + 8*LDA + 4];
            }
            #pragma unroll
            for (int nt = 0; nt < 4; nt++){
                int c0 = (wn*32 + nt*8 + g)*LDA + ks*8 + t4;
                bfr[nt][0] = B0[c0];
                bfr[nt][1] = B0[c0 + 4];
            }
            #pragma unroll
            for (int mt = 0; mt < 4; mt++)
                #pragma unroll
                for (int nt = 0; nt < 4; nt++)
                    mma8(fr.acc[mt][nt], afr[mt], bfr[nt]);
        }
        __syncthreads();
    }
}

// ---------------- mlp1: grouped GEMM + swiglu ----------------
__global__ __launch_bounds__(256) void mlp1_kernel(const float* __restrict__ w1,
                                                   const float* __restrict__ b1){
    int mt_ = blockIdx.x;
    if (mt_ >= g_numtiles) return;
    int e        = g_tile_e[mt_];
    int rowstart = g_tile_row[mt_];
    int rcnt     = g_tile_cnt[mt_];
    int nb       = blockIdx.y;            // 16 tiles of 128 w1 rows

    extern __shared__ float smem[];
    float* sA = smem;
    float* sB = smem + 2*STAGE_F;
    int*   sPair = (int*)(smem + 4*STAGE_F);
    float* sWgt  = (float*)(sPair + BM);

    int tx = threadIdx.x;
    if (tx < BM){
        int p = (tx < rcnt) ? g_perm[rowstart + tx] : -1;
        sPair[tx] = p;
        sWgt[tx]  = (p >= 0) ? g_wt[p] : 0.f;
    }
    __syncthreads();

    const float* W = w1 + (size_t)e*(2*FD)*HD + (size_t)(nb*BN)*HD;
    Frag fr;
    gemm_mainloop(sA, sB, sPair, g_t, 1, W, fr, tx);

    int w  = tx >> 5, lane = tx & 31;
    int g  = lane >> 2, t4 = lane & 3;
    int wm = w & 1, wn = w >> 1;
    const float* b1e = b1 + (size_t)e*(2*FD);

    #pragma unroll
    for (int nt = 0; nt < 4; nt++){
        int colb = nb*BN + wn*32 + nt*8 + 2*t4;      // even
        float bg = b1e[colb], bl = b1e[colb+1];
        int f = colb >> 1;
        #pragma unroll
        for (int mt = 0; mt < 4; mt++){
            #pragma unroll
            for (int half = 0; half < 2; half++){
                int row = wm*64 + mt*16 + g + half*8;
                int p = sPair[row];
                if (p < 0) continue;
                float wg = sWgt[row];
                float d0 = fr.acc[mt][nt][2*half+0] + bg;
                float d1 = fr.acc[mt][nt][2*half+1] + bl;
                float glu = fminf(d0, 7.0f);
                float lin = fminf(fmaxf(d1, -7.0f), 7.0f);
                float sg  = 1.f/(1.f + expf(-1.702f*glu));
                g_act[(size_t)p*FD + f] = glu*sg*(lin + 1.f)*wg;
            }
        }
    }
}

// ---------------- mlp2: grouped GEMM + scatter-add ----------------
__global__ __launch_bounds__(256) void mlp2_kernel(const float* __restrict__ w2,
                                                   const float* __restrict__ b2,
                                                   float* __restrict__ out){
    int mt_ = blockIdx.x;
    if (mt_ >= g_numtiles) return;
    int e        = g_tile_e[mt_];
    int rowstart = g_tile_row[mt_];
    int rcnt     = g_tile_cnt[mt_];
    int nb       = blockIdx.y;            // 8 tiles of 128 H outputs

    extern __shared__ float smem[];
    float* sA = smem;
    float* sB = smem + 2*STAGE_F;
    int*   sPair = (int*)(smem + 4*STAGE_F);
    float* sWgt  = (float*)(sPair + BM);

    int tx = threadIdx.x;
    if (tx < BM){
        int p = (tx < rcnt) ? g_perm[rowstart + tx] : -1;
        sPair[tx] = p;
        sWgt[tx]  = (p >= 0) ? g_wt[p] : 0.f;
    }
    __syncthreads();

    const float* W = w2 + (size_t)e*HD*FD + (size_t)(nb*BN)*FD;
    Frag fr;
    gemm_mainloop(sA, sB, sPair, g_act, 0, W, fr, tx);

    int w  = tx >> 5, lane = tx & 31;
    int g  = lane >> 2, t4 = lane & 3;
    int wm = w & 1, wn = w >> 1;
    const float* b2e = b2 + (size_t)e*HD;

    #pragma unroll
    for (int nt = 0; nt < 4; nt++){
        int colb = nb*BN + wn*32 + nt*8 + 2*t4;
        float bb0 = b2e[colb], bb1 = b2e[colb+1];
        #pragma unroll
        for (int mt = 0; mt < 4; mt++){
            #pragma unroll
            for (int half = 0; half < 2; half++){
                int row = wm*64 + mt*16 + g + half*8;
                int p = sPair[row];
                if (p < 0) continue;
                int tok = p >> 2;
                float wg = sWgt[row];
                float* o = out + (size_t)tok*HD + colb;
                atomicAdd(o,     fr.acc[mt][nt][2*half+0] + wg*bb0);
                atomicAdd(o + 1, fr.acc[mt][nt][2*half+1] + wg*bb1);
            }
        }
    }
}

// ---------------- launch ----------------
extern "C" void kernel_launch(void* const* d_in, const int* in_sizes, int n_in,
                              void* d_out, int out_size){
    const float* x      = (const float*)d_in[0];
    const float* nscale = (const float*)d_in[1];
    const float* gw     = (const float*)d_in[2];
    const float* gb     = (const float*)d_in[3];
    const float* w1     = (const float*)d_in[4];
    const float* b1     = (const float*)d_in[5];
    const float* w2     = (const float*)d_in[6];
    const float* b2     = (const float*)d_in[7];
    float* out = (float*)d_out;

    const int smem_bytes = (4*STAGE_F)*4 + BM*4 + BM*4;   // 73728 + 1024
    static int configured = 0;
    if (!configured){
        cudaFuncSetAttribute(mlp1_kernel, cudaFuncAttributeMaxDynamicSharedMemorySize, smem_bytes);
        cudaFuncSetAttribute(mlp2_kernel, cudaFuncAttributeMaxDynamicSharedMemorySize, smem_bytes);
        configured = 1;
    }

    init_kernel   <<<(T*HD + 255)/256, 256>>>(x, out);
    route_kernel  <<<T, 256>>>(x, nscale, gw, gb);
    scan_kernel   <<<1, 1>>>();
    scatter_kernel<<<(NPAIR + 255)/256, 256>>>();
    mlp1_kernel   <<<dim3(MT_MAX, (2*FD)/BN), 256, smem_bytes>>>(w1, b1);
    mlp2_kernel   <<<dim3(MT_MAX, HD/BN),     256, smem_bytes>>>(w2, b2, out);
}